// round 3
// baseline (speedup 1.0000x reference)
#include <cuda_runtime.h>
#include <cuda_bf16.h>

#define T_LEN 2048
#define VOCAB 1000

typedef unsigned long long ull;

// Gate table: tbl[tok*8 + g] = (i_g*0.5, f_g*0.5, g_g, o_g*0.5) as float4.
// Byte layout: first 8B = (i,f) pair, second 8B = (g,o) pair -> free f32x2 reinterp.
__device__ float4 d_tbl4[VOCAB * 8];

__global__ void build_table_kernel(const float* __restrict__ emb,
                                   const float* __restrict__ W_ih,
                                   const float* __restrict__ b_ih,
                                   const float* __restrict__ b_hh) {
    int tok = blockIdx.x;
    int j = threadIdx.x;  // gate index 0..31 (q*8+g)
    __shared__ float e[8];
    if (j < 8) e[j] = emb[tok * 8 + j];
    __syncthreads();
    float s = b_ih[j] + b_hh[j];
#pragma unroll
    for (int k = 0; k < 8; k++)
        s = fmaf(W_ih[j * 8 + k], e[k], s);
    int g = j & 7;
    int q = j >> 3;
    if (q != 2) s *= 0.5f;  // prescale sigmoid gates (i, f, o)
    reinterpret_cast<float*>(d_tbl4)[tok * 32 + g * 4 + q] = s;
}

__device__ __forceinline__ float tanha(float x) {
    float r;
    asm("tanh.approx.f32 %0, %1;" : "=f"(r) : "f"(x));
    return r;
}
// input already prescaled by 0.5: sigmoid(2a)
__device__ __forceinline__ float sigm_pre(float a) {
    return fmaf(tanha(a), 0.5f, 0.5f);
}

// ---- f32x2 packed helpers (FFMA2: one issue slot, two fp32 FMAs) ----
__device__ __forceinline__ ull packf2(float lo, float hi) {
    ull r;
    asm("mov.b64 %0, {%1, %2};" : "=l"(r) : "r"(__float_as_uint(lo)), "r"(__float_as_uint(hi)));
    return r;
}
__device__ __forceinline__ ull dupf2(float v) {
    ull r;
    asm("mov.b64 %0, {%1, %1};" : "=l"(r) : "r"(__float_as_uint(v)));
    return r;
}
__device__ __forceinline__ void unpackf2(ull p, float& lo, float& hi) {
    unsigned a, b;
    asm("mov.b64 {%0, %1}, %2;" : "=r"(a), "=r"(b) : "l"(p));
    lo = __uint_as_float(a);
    hi = __uint_as_float(b);
}
__device__ __forceinline__ void fma2(ull& d, ull a, ull b, ull c) {
    asm("fma.rn.f32x2 %0, %1, %2, %3;" : "=l"(d) : "l"(a), "l"(b), "l"(c));
}
__device__ __forceinline__ void add2(ull& d, ull a, ull b) {
    asm("add.rn.f32x2 %0, %1, %2;" : "=l"(d) : "l"(a), "l"(b));
}

__global__ void __launch_bounds__(256)
lstm_scan_kernel(const int* __restrict__ x,
                 const float* __restrict__ W_hh,
                 const float* __restrict__ W_cls,
                 const float* __restrict__ b_cls,
                 float* __restrict__ out) {
    extern __shared__ float4 stbl[];  // VOCAB*8 float4 = 128 KB

    for (int i = threadIdx.x; i < VOCAB * 8; i += blockDim.x)
        stbl[i] = d_tbl4[i];
    __syncthreads();

    int tid = blockIdx.x * blockDim.x + threadIdx.x;
    int b = tid >> 3;      // batch element
    int g = tid & 7;       // hidden unit owned by this lane

    // W_hh rows packed pairwise: wif[k] = (w_i[k]*.5, w_f[k]*.5), wgo[k] = (w_g[k], w_o[k]*.5)
    ull wif[8], wgo[8];
#pragma unroll
    for (int k = 0; k < 8; k++) {
        float wi = 0.5f * W_hh[(0 * 8 + g) * 8 + k];
        float wf = 0.5f * W_hh[(1 * 8 + g) * 8 + k];
        float wg =        W_hh[(2 * 8 + g) * 8 + k];
        float wo = 0.5f * W_hh[(3 * 8 + g) * 8 + k];
        wif[k] = packf2(wi, wf);
        wgo[k] = packf2(wg, wo);
    }

    const int4* xr4 = reinterpret_cast<const int4*>(x + (size_t)b * T_LEN);

    float c = 0.0f, h = 0.0f;
    const ull ZERO2 = 0ull;

    const int NCHUNK = T_LEN / 4;
    int4 cur = xr4[0];
    int4 nxt = xr4[1];
    float4 xg = stbl[(unsigned)cur.x * 8u + g];  // row for t=0

    for (int ch = 0; ch < NCHUNK; ch++) {
        int pf = ch + 2;
        if (pf >= NCHUNK) pf = NCHUNK - 1;  // clamp; garbage prefetch discarded
        int4 nxt2 = xr4[pf];

#pragma unroll
        for (int j = 0; j < 4; j++) {
            int ntok;
            if (j == 0)      ntok = cur.y;
            else if (j == 1) ntok = cur.z;
            else if (j == 2) ntok = cur.w;
            else             ntok = nxt.x;
            float4 xgn = stbl[(unsigned)ntok * 8u + g];  // smem, 1-step prefetch

            // gates = xg + W_hh @ h, packed f32x2: acc_if=(i,f), acc_go=(g,o)
            ull acc_if = packf2(xg.x, xg.y);
            ull acc_go = packf2(xg.z, xg.w);
            ull p_if = ZERO2, p_go = ZERO2;
#pragma unroll
            for (int k = 0; k < 4; k++) {
                ull hk2 = dupf2(__shfl_sync(0xffffffffu, h, k, 8));
                fma2(acc_if, wif[k], hk2, acc_if);
                fma2(acc_go, wgo[k], hk2, acc_go);
            }
#pragma unroll
            for (int k = 4; k < 8; k++) {
                ull hk2 = dupf2(__shfl_sync(0xffffffffu, h, k, 8));
                fma2(p_if, wif[k], hk2, p_if);
                fma2(p_go, wgo[k], hk2, p_go);
            }
            add2(acc_if, acc_if, p_if);
            add2(acc_go, acc_go, p_go);

            float a_i, a_f, a_g, a_o;
            unpackf2(acc_if, a_i, a_f);
            unpackf2(acc_go, a_g, a_o);

            float ig = sigm_pre(a_i);
            float fg = sigm_pre(a_f);
            float gg = tanha(a_g);
            float og = sigm_pre(a_o);
            c = fmaf(fg, c, ig * gg);
            h = og * tanha(c);

            xg = xgn;
        }
        cur = nxt;
        nxt = nxt2;
    }

    // classifier head: out[b] = sigmoid(sum_g h_g * W_cls[g] + b_cls)
    float v = h * W_cls[g];
    v += __shfl_xor_sync(0xffffffffu, v, 4, 8);
    v += __shfl_xor_sync(0xffffffffu, v, 2, 8);
    v += __shfl_xor_sync(0xffffffffu, v, 1, 8);
    if (g == 0) {
        float z = v + b_cls[0];
        out[b] = 1.0f / (1.0f + __expf(-z));
    }
}

extern "C" void kernel_launch(void* const* d_in, const int* in_sizes, int n_in,
                              void* d_out, int out_size) {
    const int*   x     = (const int*)d_in[0];
    const float* emb   = (const float*)d_in[1];
    const float* W_ih  = (const float*)d_in[2];
    const float* W_hh  = (const float*)d_in[3];
    const float* b_ih  = (const float*)d_in[4];
    const float* b_hh  = (const float*)d_in[5];
    const float* W_cls = (const float*)d_in[6];
    const float* b_cls = (const float*)d_in[7];
    float* out = (float*)d_out;

    int B = in_sizes[0] / T_LEN;  // 4096

    build_table_kernel<<<VOCAB, 32>>>(emb, W_ih, b_ih, b_hh);

    size_t smem = (size_t)VOCAB * 8 * sizeof(float4);  // 128000 B
    cudaFuncSetAttribute(lstm_scan_kernel,
                         cudaFuncAttributeMaxDynamicSharedMemorySize, (int)smem);

    int threads = B * 8;            // 32768
    int block = 256;
    int grid = threads / block;     // 128 blocks, 1 per SM, single wave
    lstm_scan_kernel<<<grid, block, smem>>>(x, W_hh, W_cls, b_cls, out);
}